// round 15
// baseline (speedup 1.0000x reference)
#include <cuda_runtime.h>
#include <math.h>
#include <stdint.h>

#define N_TOK 4096   // B*T
#define DIM   1024   // D
#define FF    4096   // F
#define NE    8      // experts
#define NA    8192   // N_TOK * topk(2)

// Static device scratch (proven passing footprint)
__device__ float g_h[(size_t)NA * FF];    // gelu(x@W1+b1) per assignment
__device__ float g_y[(size_t)NA * DIM];   // gated FFN2 out per slot
__device__ int   g_cnt[NE];
__device__ int   g_rows[NE * N_TOK];
__device__ float g_gate[NA];

// ---- packed fp32x2 helpers (sm_100+, PTX 8.6) ----
#define FMA2(d, a, b) \
    asm("fma.rn.f32x2 %0, %1, %2, %0;" : "+l"(d) : "l"(a), "l"(b))
#define PACKDUP(p, f) \
    asm("mov.b64 %0, {%1, %1};" : "=l"(p) : "f"(f))
#define UNPACK2(lo, hi, p) \
    asm("mov.b64 {%0, %1}, %2;" : "=f"(lo), "=f"(hi) : "l"(p))

// ---- cp.async (16B, .cg) ----
__device__ __forceinline__ uint32_t smem_u32(const void* p) {
    uint32_t a;
    asm("{ .reg .u64 t; cvta.to.shared.u64 t, %1; cvt.u32.u64 %0, t; }" : "=r"(a) : "l"(p));
    return a;
}
#define CPASYNC16(dst_u32, src) \
    asm volatile("cp.async.cg.shared.global [%0], [%1], 16;" :: "r"(dst_u32), "l"(src))
#define CP_COMMIT() asm volatile("cp.async.commit_group;")
#define CP_WAIT0()  asm volatile("cp.async.wait_group 0;")
#define CP_WAIT1()  asm volatile("cp.async.wait_group 1;")

// B stage stride in bytes: 16 rows x 132 floats x 4 B
#define BSTAGE_B (16 * 132 * 4)

__global__ void zero_cnt_kernel() {
    if (threadIdx.x < NE) g_cnt[threadIdx.x] = 0;
}

// One warp per token: logits, top-2, 2-way softmax, scatter (verbatim R1)
__global__ void gate_kernel(const float* __restrict__ x, const float* __restrict__ Wg) {
    int warp = (blockIdx.x * blockDim.x + threadIdx.x) >> 5;
    int lane = threadIdx.x & 31;
    if (warp >= N_TOK) return;
    const float* xr = x + (size_t)warp * DIM;
    float acc[NE];
#pragma unroll
    for (int e = 0; e < NE; e++) acc[e] = 0.f;
    for (int d = lane * 4; d < DIM; d += 128) {
        float4 xv = *(const float4*)(xr + d);
        float xs[4] = {xv.x, xv.y, xv.z, xv.w};
#pragma unroll
        for (int j = 0; j < 4; j++) {
            const float* wr = Wg + (size_t)(d + j) * NE;
#pragma unroll
            for (int e = 0; e < NE; e++) acc[e] += xs[j] * wr[e];
        }
    }
#pragma unroll
    for (int e = 0; e < NE; e++) {
#pragma unroll
        for (int o = 16; o > 0; o >>= 1)
            acc[e] += __shfl_xor_sync(0xffffffffu, acc[e], o);
    }
    if (lane == 0) {
        int i0 = 0; float v0 = acc[0];
#pragma unroll
        for (int e = 1; e < NE; e++) if (acc[e] > v0) { v0 = acc[e]; i0 = e; }
        int i1 = -1; float v1 = -1e30f;
#pragma unroll
        for (int e = 0; e < NE; e++) if (e != i0 && acc[e] > v1) { v1 = acc[e]; i1 = e; }
        float e1 = expf(v1 - v0);
        float inv = 1.f / (1.f + e1);
        int a0 = warp * 2, a1 = warp * 2 + 1;
        g_gate[a0] = inv;
        g_gate[a1] = e1 * inv;
        int p0 = atomicAdd(&g_cnt[i0], 1);
        g_rows[i0 * N_TOK + p0] = a0;
        int p1 = atomicAdd(&g_cnt[i1], 1);
        g_rows[i1 * N_TOK + p1] = a1;
    }
}

__device__ __forceinline__ float gelu_tanh(float v) {
    float u = 0.7978845608028654f * (v + 0.044715f * v * v * v);
    return 0.5f * v * (1.f + tanhf(u));
}

// FFN1: H[rows,FF] = gelu(Xg[rows,DIM] @ W1_e + b1_e)
// 128x128 tile, BK=16, 256 threads, 8x8/thread via fp32x2 FMA.
// 3-stage cp.async B ring (prefetch distance 2) + 2-stage A + k-frag pipelining.
__global__ __launch_bounds__(256)
void ffn1_kernel(const float* __restrict__ x, const float* __restrict__ W1,
                 const float* __restrict__ b1) {
    int e = blockIdx.z;
    int cnt = g_cnt[e];
    int row0 = blockIdx.y * 128;
    if (row0 >= cnt) return;
    int col0 = blockIdx.x * 128;
    const float* Bw = W1 + (size_t)e * DIM * FF;

    __shared__ float As[2][16][132];   // [k][m], padded
    __shared__ float Bs[3][16][132];   // [k][n], padded, 3-stage ring

    int tid = threadIdx.x;
    int tx = tid & 15, ty = tid >> 4;
    int aRow = tid >> 1, aK = (tid & 1) * 8;
    int bK = tid >> 4, bN = (tid & 15) * 8;

    const float* arow;
    {
        int gr = row0 + aRow;
        int rr = (gr < cnt) ? gr : row0;   // clamp; junk rows skipped in epilogue
        int a = g_rows[e * N_TOK + rr];
        arow = x + (size_t)(a >> 1) * DIM; // token = slot >> 1
    }
    const float* bsrc = Bw + (size_t)bK * FF + col0 + bN;
    uint32_t bdst = smem_u32(&Bs[0][bK][bN]);   // stage s: bdst + s*BSTAGE_B

    unsigned long long acc2[8][4];
#pragma unroll
    for (int i = 0; i < 8; i++)
#pragma unroll
        for (int j = 0; j < 4; j++) acc2[i][j] = 0ull;

    // prologue: B chunks 0,1 in flight; A chunk 0 staged
    {
        CPASYNC16(bdst, bsrc);
        CPASYNC16(bdst + 16, bsrc + 4);
        CP_COMMIT();
        CPASYNC16(bdst + BSTAGE_B, bsrc + (size_t)16 * FF);
        CPASYNC16(bdst + BSTAGE_B + 16, bsrc + (size_t)16 * FF + 4);
        CP_COMMIT();
        float4 pa0 = *(const float4*)(arow + aK);
        float4 pa1 = *(const float4*)(arow + aK + 4);
        As[0][aK + 0][aRow] = pa0.x; As[0][aK + 1][aRow] = pa0.y;
        As[0][aK + 2][aRow] = pa0.z; As[0][aK + 3][aRow] = pa0.w;
        As[0][aK + 4][aRow] = pa1.x; As[0][aK + 5][aRow] = pa1.y;
        As[0][aK + 6][aRow] = pa1.z; As[0][aK + 7][aRow] = pa1.w;
        CP_WAIT1();   // chunk 0's B complete; chunk 1's may remain in flight
    }
    __syncthreads();

    const int NCH = DIM / 16;   // 64
    int bbuf = 0;               // B ring index = i % 3
    for (int i = 0; i < NCH; i++) {
        int abuf = i & 1, anext = abuf ^ 1;
        bool more  = (i + 1 < NCH);
        bool more2 = (i + 2 < NCH);
        if (more2) {
            int k0 = (i + 2) * 16;
            int bw = bbuf + 2; if (bw >= 3) bw -= 3;
            CPASYNC16(bdst + bw * BSTAGE_B, bsrc + (size_t)k0 * FF);
            CPASYNC16(bdst + bw * BSTAGE_B + 16, bsrc + (size_t)k0 * FF + 4);
            CP_COMMIT();
        }
        float4 na0 = make_float4(0.f, 0.f, 0.f, 0.f), na1 = na0;
        if (more) {
            int k0 = (i + 1) * 16;
            na0 = *(const float4*)(arow + k0 + aK);
            na1 = *(const float4*)(arow + k0 + aK + 4);
        }
        // ---- fragment-pipelined compute over 16 k (verbatim R12) ----
        float arf[2][8];
        ulonglong2 bbf0[2], bbf1[2];
        *(float4*)&arf[0][0] = *(const float4*)&As[abuf][0][ty * 4];
        *(float4*)&arf[0][4] = *(const float4*)&As[abuf][0][64 + ty * 4];
        bbf0[0] = *(const ulonglong2*)&Bs[bbuf][0][tx * 4];
        bbf1[0] = *(const ulonglong2*)&Bs[bbuf][0][64 + tx * 4];
#pragma unroll
        for (int k = 0; k < 16; k++) {
            int cur = k & 1, nxt = cur ^ 1;
            if (k < 15) {
                *(float4*)&arf[nxt][0] = *(const float4*)&As[abuf][k + 1][ty * 4];
                *(float4*)&arf[nxt][4] = *(const float4*)&As[abuf][k + 1][64 + ty * 4];
                bbf0[nxt] = *(const ulonglong2*)&Bs[bbuf][k + 1][tx * 4];
                bbf1[nxt] = *(const ulonglong2*)&Bs[bbuf][k + 1][64 + tx * 4];
            }
#pragma unroll
            for (int ii = 0; ii < 8; ii++) {
                unsigned long long ap;
                PACKDUP(ap, arf[cur][ii]);
                FMA2(acc2[ii][0], ap, bbf0[cur].x);
                FMA2(acc2[ii][1], ap, bbf0[cur].y);
                FMA2(acc2[ii][2], ap, bbf1[cur].x);
                FMA2(acc2[ii][3], ap, bbf1[cur].y);
            }
        }
        if (more) {
            As[anext][aK + 0][aRow] = na0.x; As[anext][aK + 1][aRow] = na0.y;
            As[anext][aK + 2][aRow] = na0.z; As[anext][aK + 3][aRow] = na0.w;
            As[anext][aK + 4][aRow] = na1.x; As[anext][aK + 5][aRow] = na1.y;
            As[anext][aK + 6][aRow] = na1.z; As[anext][aK + 7][aRow] = na1.w;
            if (more2) CP_WAIT1(); else CP_WAIT0();
            __syncthreads();
        }
        bbuf = (bbuf + 1 == 3) ? 0 : bbuf + 1;
    }

#pragma unroll
    for (int i = 0; i < 8; i++) {
        int lr = (i < 4) ? (ty * 4 + i) : (64 + ty * 4 + i - 4);
        int r = row0 + lr;
        if (r >= cnt) continue;
        int a = g_rows[e * N_TOK + r];
        float* hrow = g_h + (size_t)a * FF + col0;
#pragma unroll
        for (int jh = 0; jh < 2; jh++) {
            int cb = jh ? (64 + tx * 4) : (tx * 4);
            float c0, c1, c2, c3;
            UNPACK2(c0, c1, acc2[i][jh * 2 + 0]);
            UNPACK2(c2, c3, acc2[i][jh * 2 + 1]);
            const float* bp = b1 + e * FF + col0 + cb;
            float4 o;
            o.x = gelu_tanh(c0 + bp[0]);
            o.y = gelu_tanh(c1 + bp[1]);
            o.z = gelu_tanh(c2 + bp[2]);
            o.w = gelu_tanh(c3 + bp[3]);
            *(float4*)(hrow + cb) = o;
        }
    }
}

// FFN2: Y[rows,DIM] = gate * (H[rows,FF] @ W2_e + b2_e)
__global__ __launch_bounds__(256)
void ffn2_kernel(const float* __restrict__ W2, const float* __restrict__ b2) {
    int e = blockIdx.z;
    int cnt = g_cnt[e];
    int row0 = blockIdx.y * 128;
    if (row0 >= cnt) return;
    int col0 = blockIdx.x * 128;
    const float* Bw = W2 + (size_t)e * FF * DIM;

    __shared__ float As[2][16][132];
    __shared__ float Bs[3][16][132];

    int tid = threadIdx.x;
    int tx = tid & 15, ty = tid >> 4;
    int aRow = tid >> 1, aK = (tid & 1) * 8;
    int bK = tid >> 4, bN = (tid & 15) * 8;

    const float* arow;
    {
        int gr = row0 + aRow;
        int rr = (gr < cnt) ? gr : row0;
        int a = g_rows[e * N_TOK + rr];
        arow = g_h + (size_t)a * FF;
    }
    const float* bsrc = Bw + (size_t)bK * DIM + col0 + bN;
    uint32_t bdst = smem_u32(&Bs[0][bK][bN]);

    unsigned long long acc2[8][4];
#pragma unroll
    for (int i = 0; i < 8; i++)
#pragma unroll
        for (int j = 0; j < 4; j++) acc2[i][j] = 0ull;

    {
        CPASYNC16(bdst, bsrc);
        CPASYNC16(bdst + 16, bsrc + 4);
        CP_COMMIT();
        CPASYNC16(bdst + BSTAGE_B, bsrc + (size_t)16 * DIM);
        CPASYNC16(bdst + BSTAGE_B + 16, bsrc + (size_t)16 * DIM + 4);
        CP_COMMIT();
        float4 pa0 = *(const float4*)(arow + aK);
        float4 pa1 = *(const float4*)(arow + aK + 4);
        As[0][aK + 0][aRow] = pa0.x; As[0][aK + 1][aRow] = pa0.y;
        As[0][aK + 2][aRow] = pa0.z; As[0][aK + 3][aRow] = pa0.w;
        As[0][aK + 4][aRow] = pa1.x; As[0][aK + 5][aRow] = pa1.y;
        As[0][aK + 6][aRow] = pa1.z; As[0][aK + 7][aRow] = pa1.w;
        CP_WAIT1();
    }
    __syncthreads();

    const int NCH = FF / 16;   // 256
    int bbuf = 0;
    for (int i = 0; i < NCH; i++) {
        int abuf = i & 1, anext = abuf ^ 1;
        bool more  = (i + 1 < NCH);
        bool more2 = (i + 2 < NCH);
        if (more2) {
            int k0 = (i + 2) * 16;
            int bw = bbuf + 2; if (bw >= 3) bw -= 3;
            CPASYNC16(bdst + bw * BSTAGE_B, bsrc + (size_t)k0 * DIM);
            CPASYNC16(bdst + bw * BSTAGE_B + 16, bsrc + (size_t)k0 * DIM + 4);
            CP_COMMIT();
        }
        float4 na0 = make_float4(0.f, 0.f, 0.f, 0.f), na1 = na0;
        if (more) {
            int k0 = (i + 1) * 16;
            na0 = *(const float4*)(arow + k0 + aK);
            na1 = *(const float4*)(arow + k0 + aK + 4);
        }
        float arf[2][8];
        ulonglong2 bbf0[2], bbf1[2];
        *(float4*)&arf[0][0] = *(const float4*)&As[abuf][0][ty * 4];
        *(float4*)&arf[0][4] = *(const float4*)&As[abuf][0][64 + ty * 4];
        bbf0[0] = *(const ulonglong2*)&Bs[bbuf][0][tx * 4];
        bbf1[0] = *(const ulonglong2*)&Bs[bbuf][0][64 + tx * 4];
#pragma unroll
        for (int k = 0; k < 16; k++) {
            int cur = k & 1, nxt = cur ^ 1;
            if (k < 15) {
                *(float4*)&arf[nxt][0] = *(const float4*)&As[abuf][k + 1][ty * 4];
                *(float4*)&arf[nxt][4] = *(const float4*)&As[abuf][k + 1][64 + ty * 4];
                bbf0[nxt] = *(const ulonglong2*)&Bs[bbuf][k + 1][tx * 4];
                bbf1[nxt] = *(const ulonglong2*)&Bs[bbuf][k + 1][64 + tx * 4];
            }
#pragma unroll
            for (int ii = 0; ii < 8; ii++) {
                unsigned long long ap;
                PACKDUP(ap, arf[cur][ii]);
                FMA2(acc2[ii][0], ap, bbf0[cur].x);
                FMA2(acc2[ii][1], ap, bbf0[cur].y);
                FMA2(acc2[ii][2], ap, bbf1[cur].x);
                FMA2(acc2[ii][3], ap, bbf1[cur].y);
            }
        }
        if (more) {
            As[anext][aK + 0][aRow] = na0.x; As[anext][aK + 1][aRow] = na0.y;
            As[anext][aK + 2][aRow] = na0.z; As[anext][aK + 3][aRow] = na0.w;
            As[anext][aK + 4][aRow] = na1.x; As[anext][aK + 5][aRow] = na1.y;
            As[anext][aK + 6][aRow] = na1.z; As[anext][aK + 7][aRow] = na1.w;
            if (more2) CP_WAIT1(); else CP_WAIT0();
            __syncthreads();
        }
        bbuf = (bbuf + 1 == 3) ? 0 : bbuf + 1;
    }

#pragma unroll
    for (int i = 0; i < 8; i++) {
        int lr = (i < 4) ? (ty * 4 + i) : (64 + ty * 4 + i - 4);
        int r = row0 + lr;
        if (r >= cnt) continue;
        int a = g_rows[e * N_TOK + r];
        float gate = g_gate[a];
        float* yrow = g_y + (size_t)a * DIM + col0;
#pragma unroll
        for (int jh = 0; jh < 2; jh++) {
            int cb = jh ? (64 + tx * 4) : (tx * 4);
            float c0, c1, c2, c3;
            UNPACK2(c0, c1, acc2[i][jh * 2 + 0]);
            UNPACK2(c2, c3, acc2[i][jh * 2 + 1]);
            const float* bp = b2 + e * DIM + col0 + cb;
            float4 o;
            o.x = gate * (c0 + bp[0]);
            o.y = gate * (c1 + bp[1]);
            o.z = gate * (c2 + bp[2]);
            o.w = gate * (c3 + bp[3]);
            *(float4*)(yrow + cb) = o;
        }
    }
}

// out[t] = y[2t] + y[2t+1]  (fixed order -> deterministic)
__global__ void combine_kernel(float* __restrict__ out) {
    int i = blockIdx.x * blockDim.x + threadIdx.x;
    if (i >= N_TOK * DIM / 4) return;
    int t = i / (DIM / 4);
    int c4 = i % (DIM / 4);
    const float4* y0 = (const float4*)(g_y + (size_t)(2 * t) * DIM) + c4;
    const float4* y1 = (const float4*)(g_y + (size_t)(2 * t + 1) * DIM) + c4;
    float4 a = *y0, b = *y1;
    ((float4*)out)[i] = make_float4(a.x + b.x, a.y + b.y, a.z + b.z, a.w + b.w);
}

extern "C" void kernel_launch(void* const* d_in, const int* in_sizes, int n_in,
                              void* d_out, int out_size) {
    const float* x  = (const float*)d_in[0];
    const float* Wg = (const float*)d_in[1];
    const float* W1 = (const float*)d_in[2];
    const float* b1 = (const float*)d_in[3];
    const float* W2 = (const float*)d_in[4];
    const float* b2 = (const float*)d_in[5];
    float* out = (float*)d_out;

    zero_cnt_kernel<<<1, 32>>>();
    gate_kernel<<<(N_TOK * 32) / 256, 256>>>(x, Wg);

    dim3 g1(FF / 128, N_TOK / 128, NE);   // (32, 32, 8)
    ffn1_kernel<<<g1, 256>>>(x, W1, b1);

    dim3 g2(DIM / 128, N_TOK / 128, NE);  // (8, 32, 8)
    ffn2_kernel<<<g2, 256>>>(W2, b2);

    combine_kernel<<<(N_TOK * DIM / 4 + 255) / 256, 256>>>(out);
}

// round 16
// speedup vs baseline: 1.0348x; 1.0348x over previous
#include <cuda_runtime.h>
#include <math.h>
#include <stdint.h>

#define N_TOK 4096   // B*T
#define DIM   1024   // D
#define FF    4096   // F
#define NE    8      // experts
#define NA    8192   // N_TOK * topk(2)

// Static device scratch (proven passing footprint)
__device__ float g_h[(size_t)NA * FF];    // gelu(x@W1+b1) per assignment
__device__ int   g_cnt[NE];
__device__ int   g_rows[NE * N_TOK];
__device__ float g_gate[NA];

// ---- packed fp32x2 helpers (sm_100+, PTX 8.6) ----
#define FMA2(d, a, b) \
    asm("fma.rn.f32x2 %0, %1, %2, %0;" : "+l"(d) : "l"(a), "l"(b))
#define PACKDUP(p, f) \
    asm("mov.b64 %0, {%1, %1};" : "=l"(p) : "f"(f))
#define UNPACK2(lo, hi, p) \
    asm("mov.b64 {%0, %1}, %2;" : "=f"(lo), "=f"(hi) : "l"(p))

// ---- cp.async (16B, .cg) ----
__device__ __forceinline__ uint32_t smem_u32(const void* p) {
    uint32_t a;
    asm("{ .reg .u64 t; cvta.to.shared.u64 t, %1; cvt.u32.u64 %0, t; }" : "=r"(a) : "l"(p));
    return a;
}
#define CPASYNC16(dst_u32, src) \
    asm volatile("cp.async.cg.shared.global [%0], [%1], 16;" :: "r"(dst_u32), "l"(src))
#define CP_COMMIT() asm volatile("cp.async.commit_group;")
#define CP_WAIT0()  asm volatile("cp.async.wait_group 0;")

__global__ void zero_cnt_kernel() {
    if (threadIdx.x < NE) g_cnt[threadIdx.x] = 0;
}

// zero-init the (poisoned) output buffer; ffn2 accumulates into it with RED.ADD
__global__ void zero_out_kernel(float* __restrict__ out) {
    int i = blockIdx.x * blockDim.x + threadIdx.x;
    if (i < N_TOK * DIM / 4)
        ((float4*)out)[i] = make_float4(0.f, 0.f, 0.f, 0.f);
}

// One warp per token: logits, top-2, 2-way softmax, scatter (verbatim R1)
__global__ void gate_kernel(const float* __restrict__ x, const float* __restrict__ Wg) {
    int warp = (blockIdx.x * blockDim.x + threadIdx.x) >> 5;
    int lane = threadIdx.x & 31;
    if (warp >= N_TOK) return;
    const float* xr = x + (size_t)warp * DIM;
    float acc[NE];
#pragma unroll
    for (int e = 0; e < NE; e++) acc[e] = 0.f;
    for (int d = lane * 4; d < DIM; d += 128) {
        float4 xv = *(const float4*)(xr + d);
        float xs[4] = {xv.x, xv.y, xv.z, xv.w};
#pragma unroll
        for (int j = 0; j < 4; j++) {
            const float* wr = Wg + (size_t)(d + j) * NE;
#pragma unroll
            for (int e = 0; e < NE; e++) acc[e] += xs[j] * wr[e];
        }
    }
#pragma unroll
    for (int e = 0; e < NE; e++) {
#pragma unroll
        for (int o = 16; o > 0; o >>= 1)
            acc[e] += __shfl_xor_sync(0xffffffffu, acc[e], o);
    }
    if (lane == 0) {
        int i0 = 0; float v0 = acc[0];
#pragma unroll
        for (int e = 1; e < NE; e++) if (acc[e] > v0) { v0 = acc[e]; i0 = e; }
        int i1 = -1; float v1 = -1e30f;
#pragma unroll
        for (int e = 0; e < NE; e++) if (e != i0 && acc[e] > v1) { v1 = acc[e]; i1 = e; }
        float e1 = expf(v1 - v0);
        float inv = 1.f / (1.f + e1);
        int a0 = warp * 2, a1 = warp * 2 + 1;
        g_gate[a0] = inv;
        g_gate[a1] = e1 * inv;
        int p0 = atomicAdd(&g_cnt[i0], 1);
        g_rows[i0 * N_TOK + p0] = a0;
        int p1 = atomicAdd(&g_cnt[i1], 1);
        g_rows[i1 * N_TOK + p1] = a1;
    }
}

__device__ __forceinline__ float gelu_tanh(float v) {
    float u = 0.7978845608028654f * (v + 0.044715f * v * v * v);
    return 0.5f * v * (1.f + tanhf(u));
}

// FFN1: H[rows,FF] = gelu(Xg[rows,DIM] @ W1_e + b1_e)       (R12 core, verbatim)
__global__ __launch_bounds__(256)
void ffn1_kernel(const float* __restrict__ x, const float* __restrict__ W1,
                 const float* __restrict__ b1) {
    int e = blockIdx.z;
    int cnt = g_cnt[e];
    int row0 = blockIdx.y * 128;
    if (row0 >= cnt) return;
    int col0 = blockIdx.x * 128;
    const float* Bw = W1 + (size_t)e * DIM * FF;

    __shared__ float As[2][16][132];   // [k][m], padded
    __shared__ float Bs[2][16][132];   // [k][n], padded

    int tid = threadIdx.x;
    int tx = tid & 15, ty = tid >> 4;
    int aRow = tid >> 1, aK = (tid & 1) * 8;
    int bK = tid >> 4, bN = (tid & 15) * 8;

    const float* arow;
    {
        int gr = row0 + aRow;
        int rr = (gr < cnt) ? gr : row0;   // clamp; junk rows skipped in epilogue
        int a = g_rows[e * N_TOK + rr];
        arow = x + (size_t)(a >> 1) * DIM; // token = slot >> 1
    }
    const float* bsrc = Bw + (size_t)bK * FF + col0 + bN;
    uint32_t bdst0[2], bdst1[2];
    bdst0[0] = smem_u32(&Bs[0][bK][bN]);     bdst1[0] = smem_u32(&Bs[0][bK][bN + 4]);
    bdst0[1] = smem_u32(&Bs[1][bK][bN]);     bdst1[1] = smem_u32(&Bs[1][bK][bN + 4]);

    unsigned long long acc2[8][4];
#pragma unroll
    for (int i = 0; i < 8; i++)
#pragma unroll
        for (int j = 0; j < 4; j++) acc2[i][j] = 0ull;

    // prologue: chunk 0 -> buf 0
    {
        CPASYNC16(bdst0[0], bsrc);
        CPASYNC16(bdst1[0], bsrc + 4);
        CP_COMMIT();
        float4 pa0 = *(const float4*)(arow + aK);
        float4 pa1 = *(const float4*)(arow + aK + 4);
        As[0][aK + 0][aRow] = pa0.x; As[0][aK + 1][aRow] = pa0.y;
        As[0][aK + 2][aRow] = pa0.z; As[0][aK + 3][aRow] = pa0.w;
        As[0][aK + 4][aRow] = pa1.x; As[0][aK + 5][aRow] = pa1.y;
        As[0][aK + 6][aRow] = pa1.z; As[0][aK + 7][aRow] = pa1.w;
        CP_WAIT0();
    }
    __syncthreads();

    const int NCH = DIM / 16;   // 64
    for (int i = 0; i < NCH; i++) {
        int buf = i & 1;
        int nbuf = buf ^ 1;
        float4 na0 = make_float4(0.f, 0.f, 0.f, 0.f), na1 = na0;
        if (i + 1 < NCH) {
            int k0 = (i + 1) * 16;
            CPASYNC16(bdst0[nbuf], bsrc + (size_t)k0 * FF);
            CPASYNC16(bdst1[nbuf], bsrc + (size_t)k0 * FF + 4);
            CP_COMMIT();
            na0 = *(const float4*)(arow + k0 + aK);
            na1 = *(const float4*)(arow + k0 + aK + 4);
        }
        // ---- fragment-pipelined compute over 16 k ----
        float arf[2][8];
        ulonglong2 bbf0[2], bbf1[2];
        *(float4*)&arf[0][0] = *(const float4*)&As[buf][0][ty * 4];
        *(float4*)&arf[0][4] = *(const float4*)&As[buf][0][64 + ty * 4];
        bbf0[0] = *(const ulonglong2*)&Bs[buf][0][tx * 4];
        bbf1[0] = *(const ulonglong2*)&Bs[buf][0][64 + tx * 4];
#pragma unroll
        for (int k = 0; k < 16; k++) {
            int cur = k & 1, nxt = cur ^ 1;
            if (k < 15) {
                *(float4*)&arf[nxt][0] = *(const float4*)&As[buf][k + 1][ty * 4];
                *(float4*)&arf[nxt][4] = *(const float4*)&As[buf][k + 1][64 + ty * 4];
                bbf0[nxt] = *(const ulonglong2*)&Bs[buf][k + 1][tx * 4];
                bbf1[nxt] = *(const ulonglong2*)&Bs[buf][k + 1][64 + tx * 4];
            }
#pragma unroll
            for (int ii = 0; ii < 8; ii++) {
                unsigned long long ap;
                PACKDUP(ap, arf[cur][ii]);
                FMA2(acc2[ii][0], ap, bbf0[cur].x);
                FMA2(acc2[ii][1], ap, bbf0[cur].y);
                FMA2(acc2[ii][2], ap, bbf1[cur].x);
                FMA2(acc2[ii][3], ap, bbf1[cur].y);
            }
        }
        if (i + 1 < NCH) {
            As[nbuf][aK + 0][aRow] = na0.x; As[nbuf][aK + 1][aRow] = na0.y;
            As[nbuf][aK + 2][aRow] = na0.z; As[nbuf][aK + 3][aRow] = na0.w;
            As[nbuf][aK + 4][aRow] = na1.x; As[nbuf][aK + 5][aRow] = na1.y;
            As[nbuf][aK + 6][aRow] = na1.z; As[nbuf][aK + 7][aRow] = na1.w;
            CP_WAIT0();
            __syncthreads();
        }
    }

#pragma unroll
    for (int i = 0; i < 8; i++) {
        int lr = (i < 4) ? (ty * 4 + i) : (64 + ty * 4 + i - 4);
        int r = row0 + lr;
        if (r >= cnt) continue;
        int a = g_rows[e * N_TOK + r];
        float* hrow = g_h + (size_t)a * FF + col0;
#pragma unroll
        for (int jh = 0; jh < 2; jh++) {
            int cb = jh ? (64 + tx * 4) : (tx * 4);
            float c0, c1, c2, c3;
            UNPACK2(c0, c1, acc2[i][jh * 2 + 0]);
            UNPACK2(c2, c3, acc2[i][jh * 2 + 1]);
            const float* bp = b1 + e * FF + col0 + cb;
            float4 o;
            o.x = gelu_tanh(c0 + bp[0]);
            o.y = gelu_tanh(c1 + bp[1]);
            o.z = gelu_tanh(c2 + bp[2]);
            o.w = gelu_tanh(c3 + bp[3]);
            *(float4*)(hrow + cb) = o;
        }
    }
}

// FFN2: out[token] += gate * (H[rows,FF] @ W2_e + b2_e)  (R12 core; fused epilogue)
__global__ __launch_bounds__(256)
void ffn2_kernel(const float* __restrict__ W2, const float* __restrict__ b2,
                 float* __restrict__ out) {
    int e = blockIdx.z;
    int cnt = g_cnt[e];
    int row0 = blockIdx.y * 128;
    if (row0 >= cnt) return;
    int col0 = blockIdx.x * 128;
    const float* Bw = W2 + (size_t)e * FF * DIM;

    __shared__ float As[2][16][132];
    __shared__ float Bs[2][16][132];

    int tid = threadIdx.x;
    int tx = tid & 15, ty = tid >> 4;
    int aRow = tid >> 1, aK = (tid & 1) * 8;
    int bK = tid >> 4, bN = (tid & 15) * 8;

    const float* arow;
    {
        int gr = row0 + aRow;
        int rr = (gr < cnt) ? gr : row0;
        int a = g_rows[e * N_TOK + rr];
        arow = g_h + (size_t)a * FF;
    }
    const float* bsrc = Bw + (size_t)bK * DIM + col0 + bN;
    uint32_t bdst0[2], bdst1[2];
    bdst0[0] = smem_u32(&Bs[0][bK][bN]);     bdst1[0] = smem_u32(&Bs[0][bK][bN + 4]);
    bdst0[1] = smem_u32(&Bs[1][bK][bN]);     bdst1[1] = smem_u32(&Bs[1][bK][bN + 4]);

    unsigned long long acc2[8][4];
#pragma unroll
    for (int i = 0; i < 8; i++)
#pragma unroll
        for (int j = 0; j < 4; j++) acc2[i][j] = 0ull;

    {
        CPASYNC16(bdst0[0], bsrc);
        CPASYNC16(bdst1[0], bsrc + 4);
        CP_COMMIT();
        float4 pa0 = *(const float4*)(arow + aK);
        float4 pa1 = *(const float4*)(arow + aK + 4);
        As[0][aK + 0][aRow] = pa0.x; As[0][aK + 1][aRow] = pa0.y;
        As[0][aK + 2][aRow] = pa0.z; As[0][aK + 3][aRow] = pa0.w;
        As[0][aK + 4][aRow] = pa1.x; As[0][aK + 5][aRow] = pa1.y;
        As[0][aK + 6][aRow] = pa1.z; As[0][aK + 7][aRow] = pa1.w;
        CP_WAIT0();
    }
    __syncthreads();

    const int NCH = FF / 16;   // 256
    for (int i = 0; i < NCH; i++) {
        int buf = i & 1;
        int nbuf = buf ^ 1;
        float4 na0 = make_float4(0.f, 0.f, 0.f, 0.f), na1 = na0;
        if (i + 1 < NCH) {
            int k0 = (i + 1) * 16;
            CPASYNC16(bdst0[nbuf], bsrc + (size_t)k0 * DIM);
            CPASYNC16(bdst1[nbuf], bsrc + (size_t)k0 * DIM + 4);
            CP_COMMIT();
            na0 = *(const float4*)(arow + k0 + aK);
            na1 = *(const float4*)(arow + k0 + aK + 4);
        }
        float arf[2][8];
        ulonglong2 bbf0[2], bbf1[2];
        *(float4*)&arf[0][0] = *(const float4*)&As[buf][0][ty * 4];
        *(float4*)&arf[0][4] = *(const float4*)&As[buf][0][64 + ty * 4];
        bbf0[0] = *(const ulonglong2*)&Bs[buf][0][tx * 4];
        bbf1[0] = *(const ulonglong2*)&Bs[buf][0][64 + tx * 4];
#pragma unroll
        for (int k = 0; k < 16; k++) {
            int cur = k & 1, nxt = cur ^ 1;
            if (k < 15) {
                *(float4*)&arf[nxt][0] = *(const float4*)&As[buf][k + 1][ty * 4];
                *(float4*)&arf[nxt][4] = *(const float4*)&As[buf][k + 1][64 + ty * 4];
                bbf0[nxt] = *(const ulonglong2*)&Bs[buf][k + 1][tx * 4];
                bbf1[nxt] = *(const ulonglong2*)&Bs[buf][k + 1][64 + tx * 4];
            }
#pragma unroll
            for (int ii = 0; ii < 8; ii++) {
                unsigned long long ap;
                PACKDUP(ap, arf[cur][ii]);
                FMA2(acc2[ii][0], ap, bbf0[cur].x);
                FMA2(acc2[ii][1], ap, bbf0[cur].y);
                FMA2(acc2[ii][2], ap, bbf1[cur].x);
                FMA2(acc2[ii][3], ap, bbf1[cur].y);
            }
        }
        if (i + 1 < NCH) {
            As[nbuf][aK + 0][aRow] = na0.x; As[nbuf][aK + 1][aRow] = na0.y;
            As[nbuf][aK + 2][aRow] = na0.z; As[nbuf][aK + 3][aRow] = na0.w;
            As[nbuf][aK + 4][aRow] = na1.x; As[nbuf][aK + 5][aRow] = na1.y;
            As[nbuf][aK + 6][aRow] = na1.z; As[nbuf][aK + 7][aRow] = na1.w;
            CP_WAIT0();
            __syncthreads();
        }
    }

    // fused epilogue: out[token] += gate * (acc + b2)   (RED.ADD, order-independent:
    // exactly two contributions per element, fp add of two operands is commutative)
#pragma unroll
    for (int i = 0; i < 8; i++) {
        int lr = (i < 4) ? (ty * 4 + i) : (64 + ty * 4 + i - 4);
        int r = row0 + lr;
        if (r >= cnt) continue;
        int a = g_rows[e * N_TOK + r];
        float gate = g_gate[a];
        float* yrow = out + (size_t)(a >> 1) * DIM + col0;   // token = slot >> 1
#pragma unroll
        for (int jh = 0; jh < 2; jh++) {
            int cb = jh ? (64 + tx * 4) : (tx * 4);
            float c0, c1, c2, c3;
            UNPACK2(c0, c1, acc2[i][jh * 2 + 0]);
            UNPACK2(c2, c3, acc2[i][jh * 2 + 1]);
            const float* bp = b2 + e * DIM + col0 + cb;
            atomicAdd(yrow + cb + 0, gate * (c0 + bp[0]));
            atomicAdd(yrow + cb + 1, gate * (c1 + bp[1]));
            atomicAdd(yrow + cb + 2, gate * (c2 + bp[2]));
            atomicAdd(yrow + cb + 3, gate * (c3 + bp[3]));
        }
    }
}

extern "C" void kernel_launch(void* const* d_in, const int* in_sizes, int n_in,
                              void* d_out, int out_size) {
    const float* x  = (const float*)d_in[0];
    const float* Wg = (const float*)d_in[1];
    const float* W1 = (const float*)d_in[2];
    const float* b1 = (const float*)d_in[3];
    const float* W2 = (const float*)d_in[4];
    const float* b2 = (const float*)d_in[5];
    float* out = (float*)d_out;

    zero_cnt_kernel<<<1, 32>>>();
    gate_kernel<<<(N_TOK * 32) / 256, 256>>>(x, Wg);
    zero_out_kernel<<<(N_TOK * DIM / 4 + 255) / 256, 256>>>(out);

    dim3 g1(FF / 128, N_TOK / 128, NE);   // (32, 32, 8)
    ffn1_kernel<<<g1, 256>>>(x, W1, b1);

    dim3 g2(DIM / 128, N_TOK / 128, NE);  // (8, 32, 8)
    ffn2_kernel<<<g2, 256>>>(W2, b2, out);
}

// round 17
// speedup vs baseline: 1.0372x; 1.0024x over previous
#include <cuda_runtime.h>
#include <math.h>
#include <stdint.h>

#define N_TOK 4096   // B*T
#define DIM   1024   // D
#define FF    4096   // F
#define NE    8      // experts
#define NA    8192   // N_TOK * topk(2)

// Static device scratch (proven passing footprint)
__device__ float g_h[(size_t)NA * FF];    // gelu(x@W1+b1) per assignment
__device__ int   g_cnt[NE];
__device__ int   g_rows[NE * N_TOK];
__device__ float g_gate[NA];

// ---- packed fp32x2 helpers (sm_100+, PTX 8.6) ----
#define FMA2(d, a, b) \
    asm("fma.rn.f32x2 %0, %1, %2, %0;" : "+l"(d) : "l"(a), "l"(b))
#define PACKDUP(p, f) \
    asm("mov.b64 %0, {%1, %1};" : "=l"(p) : "f"(f))
#define UNPACK2(lo, hi, p) \
    asm("mov.b64 {%0, %1}, %2;" : "=f"(lo), "=f"(hi) : "l"(p))

// ---- cp.async (16B, .cg) ----
__device__ __forceinline__ uint32_t smem_u32(const void* p) {
    uint32_t a;
    asm("{ .reg .u64 t; cvta.to.shared.u64 t, %1; cvt.u32.u64 %0, t; }" : "=r"(a) : "l"(p));
    return a;
}
#define CPASYNC16(dst_u32, src) \
    asm volatile("cp.async.cg.shared.global [%0], [%1], 16;" :: "r"(dst_u32), "l"(src))
#define CP_COMMIT() asm volatile("cp.async.commit_group;")
#define CP_WAIT0()  asm volatile("cp.async.wait_group 0;")

__global__ void zero_cnt_kernel() {
    if (threadIdx.x < NE) g_cnt[threadIdx.x] = 0;
}

// One warp per token: zero the token's output row (overlapped with gating),
// then logits, top-2, 2-way softmax, scatter. Gating math verbatim R1.
__global__ void gate_kernel(const float* __restrict__ x, const float* __restrict__ Wg,
                            float* __restrict__ out) {
    int warp = (blockIdx.x * blockDim.x + threadIdx.x) >> 5;
    int lane = threadIdx.x & 31;
    if (warp >= N_TOK) return;

    // zero out[token] row: 1024 floats = 32 lanes x 8 float4
    {
        float4* orow = (float4*)(out + (size_t)warp * DIM);
        const float4 z = make_float4(0.f, 0.f, 0.f, 0.f);
#pragma unroll
        for (int j = 0; j < 8; j++) orow[lane + j * 32] = z;
    }

    const float* xr = x + (size_t)warp * DIM;
    float acc[NE];
#pragma unroll
    for (int e = 0; e < NE; e++) acc[e] = 0.f;
    for (int d = lane * 4; d < DIM; d += 128) {
        float4 xv = *(const float4*)(xr + d);
        float xs[4] = {xv.x, xv.y, xv.z, xv.w};
#pragma unroll
        for (int j = 0; j < 4; j++) {
            const float* wr = Wg + (size_t)(d + j) * NE;
#pragma unroll
            for (int e = 0; e < NE; e++) acc[e] += xs[j] * wr[e];
        }
    }
#pragma unroll
    for (int e = 0; e < NE; e++) {
#pragma unroll
        for (int o = 16; o > 0; o >>= 1)
            acc[e] += __shfl_xor_sync(0xffffffffu, acc[e], o);
    }
    if (lane == 0) {
        int i0 = 0; float v0 = acc[0];
#pragma unroll
        for (int e = 1; e < NE; e++) if (acc[e] > v0) { v0 = acc[e]; i0 = e; }
        int i1 = -1; float v1 = -1e30f;
#pragma unroll
        for (int e = 0; e < NE; e++) if (e != i0 && acc[e] > v1) { v1 = acc[e]; i1 = e; }
        float e1 = expf(v1 - v0);
        float inv = 1.f / (1.f + e1);
        int a0 = warp * 2, a1 = warp * 2 + 1;
        g_gate[a0] = inv;
        g_gate[a1] = e1 * inv;
        int p0 = atomicAdd(&g_cnt[i0], 1);
        g_rows[i0 * N_TOK + p0] = a0;
        int p1 = atomicAdd(&g_cnt[i1], 1);
        g_rows[i1 * N_TOK + p1] = a1;
    }
}

__device__ __forceinline__ float gelu_tanh(float v) {
    float u = 0.7978845608028654f * (v + 0.044715f * v * v * v);
    return 0.5f * v * (1.f + tanhf(u));
}

// FFN1: H[rows,FF] = gelu(Xg[rows,DIM] @ W1_e + b1_e)       (R12/R16 core, verbatim)
__global__ __launch_bounds__(256)
void ffn1_kernel(const float* __restrict__ x, const float* __restrict__ W1,
                 const float* __restrict__ b1) {
    int e = blockIdx.z;
    int cnt = g_cnt[e];
    int row0 = blockIdx.y * 128;
    if (row0 >= cnt) return;
    int col0 = blockIdx.x * 128;
    const float* Bw = W1 + (size_t)e * DIM * FF;

    __shared__ float As[2][16][132];   // [k][m], padded
    __shared__ float Bs[2][16][132];   // [k][n], padded

    int tid = threadIdx.x;
    int tx = tid & 15, ty = tid >> 4;
    int aRow = tid >> 1, aK = (tid & 1) * 8;
    int bK = tid >> 4, bN = (tid & 15) * 8;

    const float* arow;
    {
        int gr = row0 + aRow;
        int rr = (gr < cnt) ? gr : row0;   // clamp; junk rows skipped in epilogue
        int a = g_rows[e * N_TOK + rr];
        arow = x + (size_t)(a >> 1) * DIM; // token = slot >> 1
    }
    const float* bsrc = Bw + (size_t)bK * FF + col0 + bN;
    uint32_t bdst0[2], bdst1[2];
    bdst0[0] = smem_u32(&Bs[0][bK][bN]);     bdst1[0] = smem_u32(&Bs[0][bK][bN + 4]);
    bdst0[1] = smem_u32(&Bs[1][bK][bN]);     bdst1[1] = smem_u32(&Bs[1][bK][bN + 4]);

    unsigned long long acc2[8][4];
#pragma unroll
    for (int i = 0; i < 8; i++)
#pragma unroll
        for (int j = 0; j < 4; j++) acc2[i][j] = 0ull;

    // prologue: chunk 0 -> buf 0
    {
        CPASYNC16(bdst0[0], bsrc);
        CPASYNC16(bdst1[0], bsrc + 4);
        CP_COMMIT();
        float4 pa0 = *(const float4*)(arow + aK);
        float4 pa1 = *(const float4*)(arow + aK + 4);
        As[0][aK + 0][aRow] = pa0.x; As[0][aK + 1][aRow] = pa0.y;
        As[0][aK + 2][aRow] = pa0.z; As[0][aK + 3][aRow] = pa0.w;
        As[0][aK + 4][aRow] = pa1.x; As[0][aK + 5][aRow] = pa1.y;
        As[0][aK + 6][aRow] = pa1.z; As[0][aK + 7][aRow] = pa1.w;
        CP_WAIT0();
    }
    __syncthreads();

    const int NCH = DIM / 16;   // 64
    for (int i = 0; i < NCH; i++) {
        int buf = i & 1;
        int nbuf = buf ^ 1;
        float4 na0 = make_float4(0.f, 0.f, 0.f, 0.f), na1 = na0;
        if (i + 1 < NCH) {
            int k0 = (i + 1) * 16;
            CPASYNC16(bdst0[nbuf], bsrc + (size_t)k0 * FF);
            CPASYNC16(bdst1[nbuf], bsrc + (size_t)k0 * FF + 4);
            CP_COMMIT();
            na0 = *(const float4*)(arow + k0 + aK);
            na1 = *(const float4*)(arow + k0 + aK + 4);
        }
        // ---- fragment-pipelined compute over 16 k ----
        float arf[2][8];
        ulonglong2 bbf0[2], bbf1[2];
        *(float4*)&arf[0][0] = *(const float4*)&As[buf][0][ty * 4];
        *(float4*)&arf[0][4] = *(const float4*)&As[buf][0][64 + ty * 4];
        bbf0[0] = *(const ulonglong2*)&Bs[buf][0][tx * 4];
        bbf1[0] = *(const ulonglong2*)&Bs[buf][0][64 + tx * 4];
#pragma unroll
        for (int k = 0; k < 16; k++) {
            int cur = k & 1, nxt = cur ^ 1;
            if (k < 15) {
                *(float4*)&arf[nxt][0] = *(const float4*)&As[buf][k + 1][ty * 4];
                *(float4*)&arf[nxt][4] = *(const float4*)&As[buf][k + 1][64 + ty * 4];
                bbf0[nxt] = *(const ulonglong2*)&Bs[buf][k + 1][tx * 4];
                bbf1[nxt] = *(const ulonglong2*)&Bs[buf][k + 1][64 + tx * 4];
            }
#pragma unroll
            for (int ii = 0; ii < 8; ii++) {
                unsigned long long ap;
                PACKDUP(ap, arf[cur][ii]);
                FMA2(acc2[ii][0], ap, bbf0[cur].x);
                FMA2(acc2[ii][1], ap, bbf0[cur].y);
                FMA2(acc2[ii][2], ap, bbf1[cur].x);
                FMA2(acc2[ii][3], ap, bbf1[cur].y);
            }
        }
        if (i + 1 < NCH) {
            As[nbuf][aK + 0][aRow] = na0.x; As[nbuf][aK + 1][aRow] = na0.y;
            As[nbuf][aK + 2][aRow] = na0.z; As[nbuf][aK + 3][aRow] = na0.w;
            As[nbuf][aK + 4][aRow] = na1.x; As[nbuf][aK + 5][aRow] = na1.y;
            As[nbuf][aK + 6][aRow] = na1.z; As[nbuf][aK + 7][aRow] = na1.w;
            CP_WAIT0();
            __syncthreads();
        }
    }

#pragma unroll
    for (int i = 0; i < 8; i++) {
        int lr = (i < 4) ? (ty * 4 + i) : (64 + ty * 4 + i - 4);
        int r = row0 + lr;
        if (r >= cnt) continue;
        int a = g_rows[e * N_TOK + r];
        float* hrow = g_h + (size_t)a * FF + col0;
#pragma unroll
        for (int jh = 0; jh < 2; jh++) {
            int cb = jh ? (64 + tx * 4) : (tx * 4);
            float c0, c1, c2, c3;
            UNPACK2(c0, c1, acc2[i][jh * 2 + 0]);
            UNPACK2(c2, c3, acc2[i][jh * 2 + 1]);
            const float* bp = b1 + e * FF + col0 + cb;
            float4 o;
            o.x = gelu_tanh(c0 + bp[0]);
            o.y = gelu_tanh(c1 + bp[1]);
            o.z = gelu_tanh(c2 + bp[2]);
            o.w = gelu_tanh(c3 + bp[3]);
            *(float4*)(hrow + cb) = o;
        }
    }
}

// FFN2: out[token] += gate * (H[rows,FF] @ W2_e + b2_e)  (R16 core, verbatim)
__global__ __launch_bounds__(256)
void ffn2_kernel(const float* __restrict__ W2, const float* __restrict__ b2,
                 float* __restrict__ out) {
    int e = blockIdx.z;
    int cnt = g_cnt[e];
    int row0 = blockIdx.y * 128;
    if (row0 >= cnt) return;
    int col0 = blockIdx.x * 128;
    const float* Bw = W2 + (size_t)e * FF * DIM;

    __shared__ float As[2][16][132];
    __shared__ float Bs[2][16][132];

    int tid = threadIdx.x;
    int tx = tid & 15, ty = tid >> 4;
    int aRow = tid >> 1, aK = (tid & 1) * 8;
    int bK = tid >> 4, bN = (tid & 15) * 8;

    const float* arow;
    {
        int gr = row0 + aRow;
        int rr = (gr < cnt) ? gr : row0;
        int a = g_rows[e * N_TOK + rr];
        arow = g_h + (size_t)a * FF;
    }
    const float* bsrc = Bw + (size_t)bK * DIM + col0 + bN;
    uint32_t bdst0[2], bdst1[2];
    bdst0[0] = smem_u32(&Bs[0][bK][bN]);     bdst1[0] = smem_u32(&Bs[0][bK][bN + 4]);
    bdst0[1] = smem_u32(&Bs[1][bK][bN]);     bdst1[1] = smem_u32(&Bs[1][bK][bN + 4]);

    unsigned long long acc2[8][4];
#pragma unroll
    for (int i = 0; i < 8; i++)
#pragma unroll
        for (int j = 0; j < 4; j++) acc2[i][j] = 0ull;

    {
        CPASYNC16(bdst0[0], bsrc);
        CPASYNC16(bdst1[0], bsrc + 4);
        CP_COMMIT();
        float4 pa0 = *(const float4*)(arow + aK);
        float4 pa1 = *(const float4*)(arow + aK + 4);
        As[0][aK + 0][aRow] = pa0.x; As[0][aK + 1][aRow] = pa0.y;
        As[0][aK + 2][aRow] = pa0.z; As[0][aK + 3][aRow] = pa0.w;
        As[0][aK + 4][aRow] = pa1.x; As[0][aK + 5][aRow] = pa1.y;
        As[0][aK + 6][aRow] = pa1.z; As[0][aK + 7][aRow] = pa1.w;
        CP_WAIT0();
    }
    __syncthreads();

    const int NCH = FF / 16;   // 256
    for (int i = 0; i < NCH; i++) {
        int buf = i & 1;
        int nbuf = buf ^ 1;
        float4 na0 = make_float4(0.f, 0.f, 0.f, 0.f), na1 = na0;
        if (i + 1 < NCH) {
            int k0 = (i + 1) * 16;
            CPASYNC16(bdst0[nbuf], bsrc + (size_t)k0 * DIM);
            CPASYNC16(bdst1[nbuf], bsrc + (size_t)k0 * DIM + 4);
            CP_COMMIT();
            na0 = *(const float4*)(arow + k0 + aK);
            na1 = *(const float4*)(arow + k0 + aK + 4);
        }
        float arf[2][8];
        ulonglong2 bbf0[2], bbf1[2];
        *(float4*)&arf[0][0] = *(const float4*)&As[buf][0][ty * 4];
        *(float4*)&arf[0][4] = *(const float4*)&As[buf][0][64 + ty * 4];
        bbf0[0] = *(const ulonglong2*)&Bs[buf][0][tx * 4];
        bbf1[0] = *(const ulonglong2*)&Bs[buf][0][64 + tx * 4];
#pragma unroll
        for (int k = 0; k < 16; k++) {
            int cur = k & 1, nxt = cur ^ 1;
            if (k < 15) {
                *(float4*)&arf[nxt][0] = *(const float4*)&As[buf][k + 1][ty * 4];
                *(float4*)&arf[nxt][4] = *(const float4*)&As[buf][k + 1][64 + ty * 4];
                bbf0[nxt] = *(const ulonglong2*)&Bs[buf][k + 1][tx * 4];
                bbf1[nxt] = *(const ulonglong2*)&Bs[buf][k + 1][64 + tx * 4];
            }
#pragma unroll
            for (int ii = 0; ii < 8; ii++) {
                unsigned long long ap;
                PACKDUP(ap, arf[cur][ii]);
                FMA2(acc2[ii][0], ap, bbf0[cur].x);
                FMA2(acc2[ii][1], ap, bbf0[cur].y);
                FMA2(acc2[ii][2], ap, bbf1[cur].x);
                FMA2(acc2[ii][3], ap, bbf1[cur].y);
            }
        }
        if (i + 1 < NCH) {
            As[nbuf][aK + 0][aRow] = na0.x; As[nbuf][aK + 1][aRow] = na0.y;
            As[nbuf][aK + 2][aRow] = na0.z; As[nbuf][aK + 3][aRow] = na0.w;
            As[nbuf][aK + 4][aRow] = na1.x; As[nbuf][aK + 5][aRow] = na1.y;
            As[nbuf][aK + 6][aRow] = na1.z; As[nbuf][aK + 7][aRow] = na1.w;
            CP_WAIT0();
            __syncthreads();
        }
    }

    // fused epilogue: out[token] += gate * (acc + b2)   (RED.ADD; exactly two
    // contributions per element -> order-independent, bitwise-deterministic)
#pragma unroll
    for (int i = 0; i < 8; i++) {
        int lr = (i < 4) ? (ty * 4 + i) : (64 + ty * 4 + i - 4);
        int r = row0 + lr;
        if (r >= cnt) continue;
        int a = g_rows[e * N_TOK + r];
        float gate = g_gate[a];
        float* yrow = out + (size_t)(a >> 1) * DIM + col0;   // token = slot >> 1
#pragma unroll
        for (int jh = 0; jh < 2; jh++) {
            int cb = jh ? (64 + tx * 4) : (tx * 4);
            float c0, c1, c2, c3;
            UNPACK2(c0, c1, acc2[i][jh * 2 + 0]);
            UNPACK2(c2, c3, acc2[i][jh * 2 + 1]);
            const float* bp = b2 + e * DIM + col0 + cb;
            atomicAdd(yrow + cb + 0, gate * (c0 + bp[0]));
            atomicAdd(yrow + cb + 1, gate * (c1 + bp[1]));
            atomicAdd(yrow + cb + 2, gate * (c2 + bp[2]));
            atomicAdd(yrow + cb + 3, gate * (c3 + bp[3]));
        }
    }
}

extern "C" void kernel_launch(void* const* d_in, const int* in_sizes, int n_in,
                              void* d_out, int out_size) {
    const float* x  = (const float*)d_in[0];
    const float* Wg = (const float*)d_in[1];
    const float* W1 = (const float*)d_in[2];
    const float* b1 = (const float*)d_in[3];
    const float* W2 = (const float*)d_in[4];
    const float* b2 = (const float*)d_in[5];
    float* out = (float*)d_out;

    zero_cnt_kernel<<<1, 32>>>();
    gate_kernel<<<(N_TOK * 32) / 256, 256>>>(x, Wg, out);

    dim3 g1(FF / 128, N_TOK / 128, NE);   // (32, 32, 8)
    ffn1_kernel<<<g1, 256>>>(x, W1, b1);

    dim3 g2(DIM / 128, N_TOK / 128, NE);  // (8, 32, 8)
    ffn2_kernel<<<g2, 256>>>(W2, b2, out);
}